// round 15
// baseline (speedup 1.0000x reference)
#include <cuda_runtime.h>
#include <cuda_bf16.h>
#include <cstdint>

#define NB 64      // batch
#define NL 512     // sequence length
#define ND 300     // embed dim
#define ND4 75     // float4 lanes per row
#define NC 128     // channels
#define CH 8       // token chunks per batch
#define TPC 64     // tokens per gather block
#define WAYS 4
#define JPER 16    // tokens per way

#define GATHER_BLOCKS (NB * CH)          // 512
#define PREP_BLOCKS   120                // 3 kk x 8 c'tiles x 5 djtiles
#define TOTAL_BLOCKS  (GATHER_BLOCKS + PREP_BLOCKS + 1)

// Scratch (__device__ globals per allocation rules)
__device__ float4 g_part4[NB * CH * 3 * ND4];  // partial g sums
__device__ float4 g_W2T4[225 * NC];            // fused weights, transposed
__device__ float  g_bias2[NC];                 // fused bias

// ---------------------------------------------------------------------------
// Mega kernel: blocks 0..511 gather (R10 verbatim);
//              blocks 512..631 prep-GEMM W2 = fc_w (x) conv_w;
//              block 632 bias2 + S_k.
// Shared smem union: gather 16.4 KB | prep 39 KB | bias 1.6 KB.
// ---------------------------------------------------------------------------
__global__ __launch_bounds__(320, 3) void mega_kernel(
    const int*   __restrict__ x,
    const float* __restrict__ embed_w,
    const float* __restrict__ conv_w,
    const float* __restrict__ conv_b,
    const float* __restrict__ fc3_w,
    const float* __restrict__ fc3_b,
    const float* __restrict__ fc4_w,
    const float* __restrict__ fc4_b,
    const float* __restrict__ fc5_w,
    const float* __restrict__ fc5_b,
    const float* __restrict__ fc_w,
    const float* __restrict__ fc_b)
{
    __shared__ __align__(16) char smu[39744];
    const int bid = blockIdx.x;
    const int tid = threadIdx.x;

    if (bid < GATHER_BLOCKS) {
        // ---------------- Gather (R10 best, verbatim) ----------------
        int*    sidx = (int*)smu;                  // [64]
        float*  sc   = (float*)(smu + 256);        // [3][64]
        float4* sred = (float4*)(smu + 1024);      // [WAYS][3][80]

        const int b     = bid >> 3;
        const int chunk = bid & 7;
        const int d4    = tid % 80;
        const int y     = tid / 80;

        if (tid < 192) {
            const int kk = tid >> 6;
            const int tt = tid & 63;
            const int t  = chunk * TPC + tt;
            const float* wk = (kk == 0) ? fc3_w : (kk == 1) ? fc4_w : fc5_w;
            const int k = kk + 3;
            int lo = t - k + 1; if (lo < 0) lo = 0;
            int hi = t; const int lim = NL - k - 1; if (hi > lim) hi = lim;
            float s = 0.f;
            #pragma unroll 5
            for (int l = lo; l <= hi; l++) s += __ldg(&wk[l]);
            sc[kk * TPC + tt] = s;
        } else if (tid < 256) {
            const int tt = tid - 192;
            sidx[tt] = __ldg(&x[b * NL + chunk * TPC + tt]);
        }
        __syncthreads();

        float4 a0 = make_float4(0.f, 0.f, 0.f, 0.f);
        float4 a1 = a0, a2 = a0;

        if (d4 < ND4) {
            const float4* emb4 = (const float4*)embed_w;
            #pragma unroll
            for (int bb = 0; bb < 2; bb++) {
                int    rix[8];
                float4 v[8];
                #pragma unroll
                for (int j = 0; j < 8; j++) rix[j] = sidx[y * JPER + bb * 8 + j];
                #pragma unroll
                for (int j = 0; j < 8; j++) v[j] = __ldg(&emb4[rix[j] * ND4 + d4]);
                #pragma unroll
                for (int j = 0; j < 8; j++) {
                    const int jj = y * JPER + bb * 8 + j;
                    const float c0 = sc[0 * TPC + jj];
                    const float c1 = sc[1 * TPC + jj];
                    const float c2 = sc[2 * TPC + jj];
                    a0.x = fmaf(c0, v[j].x, a0.x); a0.y = fmaf(c0, v[j].y, a0.y);
                    a0.z = fmaf(c0, v[j].z, a0.z); a0.w = fmaf(c0, v[j].w, a0.w);
                    a1.x = fmaf(c1, v[j].x, a1.x); a1.y = fmaf(c1, v[j].y, a1.y);
                    a1.z = fmaf(c1, v[j].z, a1.z); a1.w = fmaf(c1, v[j].w, a1.w);
                    a2.x = fmaf(c2, v[j].x, a2.x); a2.y = fmaf(c2, v[j].y, a2.y);
                    a2.z = fmaf(c2, v[j].z, a2.z); a2.w = fmaf(c2, v[j].w, a2.w);
                }
            }
        }
        sred[(y * 3 + 0) * 80 + d4] = a0;
        sred[(y * 3 + 1) * 80 + d4] = a1;
        sred[(y * 3 + 2) * 80 + d4] = a2;
        __syncthreads();

        if (tid < 240) {
            const int kk = tid / 80;
            const int dd = tid % 80;
            if (dd < ND4) {
                float4 s = sred[(0 * 3 + kk) * 80 + dd];
                #pragma unroll
                for (int w = 1; w < WAYS; w++) {
                    const float4 v = sred[(w * 3 + kk) * 80 + dd];
                    s.x += v.x; s.y += v.y; s.z += v.z; s.w += v.w;
                }
                g_part4[((b * CH + chunk) * 3 + kk) * ND4 + dd] = s;
            }
        }
    } else if (bid < GATHER_BLOCKS + PREP_BLOCKS) {
        // ---------------- Prep GEMM: W2T[idx][c'] ----------------
        // block = (kk, c'tile of 16, djtile of 15); inner dim 128.
        const int pb  = bid - GATHER_BLOCKS;
        const int kk  = pb / 40;
        const int rem = pb % 40;
        const int ct  = rem / 5;
        const int dt  = rem % 5;

        float*  A  = (float*)smu;                  // [16][129] padded
        float4* Bt = (float4*)(smu + 8256);        // [128][15]

        // Stage A = fc_w[ct*16 + r][kk*128 + cc], coalesced per row
        for (int i = tid; i < 16 * 128; i += 320) {
            const int r = i >> 7, cc = i & 127;
            A[r * 129 + cc] = __ldg(&fc_w[(ct * 16 + r) * 384 + kk * 128 + cc]);
        }
        // Stage B = conv_w4[cc][dt*15 + j]
        {
            const float4* cw4 = (const float4*)conv_w;
            for (int i = tid; i < 128 * 15; i += 320) {
                const int cc = i / 15, j = i - cc * 15;
                Bt[cc * 15 + j] = __ldg(&cw4[cc * ND4 + dt * 15 + j]);
            }
        }
        __syncthreads();

        if (tid < 240) {
            const int r = tid / 15, j = tid - (tid / 15) * 15;
            float4 acc = make_float4(0.f, 0.f, 0.f, 0.f);
            #pragma unroll 8
            for (int cc = 0; cc < 128; cc++) {
                const float  a = A[r * 129 + cc];
                const float4 v = Bt[cc * 15 + j];
                acc.x = fmaf(a, v.x, acc.x); acc.y = fmaf(a, v.y, acc.y);
                acc.z = fmaf(a, v.z, acc.z); acc.w = fmaf(a, v.w, acc.w);
            }
            g_W2T4[(kk * 75 + dt * 15 + j) * NC + ct * 16 + r] = acc;
        }
    } else {
        // ---------------- bias2 + S_k ----------------
        float* coefvec = (float*)smu;          // [384]
        float* sSk     = (float*)(smu + 1536); // [3]
        const int warp = tid >> 5;
        const int lane = tid & 31;

        if (warp < 3) {
            const float* wks[3] = {fc3_w, fc4_w, fc5_w};
            const float* w = wks[warp];
            const int n = NL - (warp + 3);
            float s = 0.f;
            for (int l = lane; l < n; l += 32) s += __ldg(&w[l]);
            #pragma unroll
            for (int off = 16; off > 0; off >>= 1)
                s += __shfl_xor_sync(0xFFFFFFFFu, s, off);
            if (lane == 0) sSk[warp] = s;
        }
        __syncthreads();

        for (int i = tid; i < 384; i += 320) {
            const int kk = i >> 7, c = i & 127;
            const float bk = (kk == 0) ? fc3_b[0] : (kk == 1) ? fc4_b[0] : fc5_b[0];
            coefvec[i] = __ldg(&conv_b[c]) * sSk[kk] + bk;
        }
        __syncthreads();

        // warp per output channel (10 warps cycle over 128 c')
        for (int cp = warp; cp < NC; cp += 10) {
            float s = 0.f;
            for (int i = lane; i < 384; i += 32)
                s += __ldg(&fc_w[cp * 384 + i]) * coefvec[i];
            #pragma unroll
            for (int off = 16; off > 0; off >>= 1)
                s += __shfl_xor_sync(0xFFFFFFFFu, s, off);
            if (lane == 0) g_bias2[cp] = s + __ldg(&fc_b[cp]);
        }
    }
}

// ---------------------------------------------------------------------------
// Final kernel: chunk-reduce g + fused dot out = W2T.g + bias2.
// grid (4 c'-tiles, 16 batch-tiles) = 64 blocks, 512 threads.
// ---------------------------------------------------------------------------
__global__ __launch_bounds__(512) void final_kernel(float* __restrict__ out)
{
    __shared__ float4 sgs[4 * 225];
    __shared__ float  qp[16 * 32];

    const int tid  = threadIdx.x;
    const int warp = tid >> 5;
    const int lane = tid & 31;
    const int c0   = blockIdx.x * 32;
    const int b0   = blockIdx.y * 4;

    for (int p = tid; p < 4 * 225; p += 512) {
        const int bs = p / 225;
        const int i  = p % 225;
        const float4* q = &g_part4[(b0 + bs) * (CH * 225) + i];
        float4 s = q[0];
        #pragma unroll
        for (int ch = 1; ch < CH; ch++) {
            const float4 v = q[ch * 225];
            s.x += v.x; s.y += v.y; s.z += v.z; s.w += v.w;
        }
        sgs[bs * 225 + i] = s;
    }
    __syncthreads();

    const int bsub = warp >> 2;
    const int q    = warp & 3;
    const int i0   = q * 56 + (q > 0);
    const int i1   = (q == 3) ? 225 : ((q + 1) * 56 + 1);
    float o = 0.f;
    #pragma unroll 4
    for (int i = i0; i < i1; i++) {
        const float4 w = __ldg(&g_W2T4[i * NC + c0 + lane]);  // coalesced
        const float4 g = sgs[bsub * 225 + i];                 // broadcast
        o = fmaf(w.x, g.x, o); o = fmaf(w.y, g.y, o);
        o = fmaf(w.z, g.z, o); o = fmaf(w.w, g.w, o);
    }
    qp[warp * 32 + lane] = o;
    __syncthreads();

    if (tid < 128) {
        const int bs = tid >> 5;
        const int ln = tid & 31;
        const float r = qp[(bs * 4 + 0) * 32 + ln] + qp[(bs * 4 + 1) * 32 + ln]
                      + qp[(bs * 4 + 2) * 32 + ln] + qp[(bs * 4 + 3) * 32 + ln];
        out[(b0 + bs) * NC + c0 + ln] = r + g_bias2[c0 + ln];
    }
}

// ---------------------------------------------------------------------------
extern "C" void kernel_launch(void* const* d_in, const int* in_sizes, int n_in,
                              void* d_out, int out_size) {
    const int*   x       = (const int*)  d_in[0];
    const float* embed_w = (const float*)d_in[1];
    const float* conv_w  = (const float*)d_in[2];
    const float* conv_b  = (const float*)d_in[3];
    const float* fc3_w   = (const float*)d_in[4];
    const float* fc3_b   = (const float*)d_in[5];
    const float* fc4_w   = (const float*)d_in[6];
    const float* fc4_b   = (const float*)d_in[7];
    const float* fc5_w   = (const float*)d_in[8];
    const float* fc5_b   = (const float*)d_in[9];
    const float* fc_w    = (const float*)d_in[10];
    const float* fc_b    = (const float*)d_in[11];
    float* out = (float*)d_out;

    mega_kernel<<<TOTAL_BLOCKS, 320>>>(x, embed_w, conv_w, conv_b,
                                       fc3_w, fc3_b, fc4_w, fc4_b,
                                       fc5_w, fc5_b, fc_w, fc_b);
    final_kernel<<<dim3(4, 16), 512>>>(out);
}

// round 16
// speedup vs baseline: 1.0011x; 1.0011x over previous
#include <cuda_runtime.h>
#include <cuda_bf16.h>
#include <cstdint>

#define NB 64      // batch
#define NL 512     // sequence length
#define ND 300     // embed dim
#define ND4 75     // float4 lanes per row
#define NC 128     // channels
#define CH 8       // token chunks per batch
#define TPC 64     // tokens per gather block
#define WAYS 4
#define JPER 16    // tokens per way

#define GATHER_BLOCKS (NB * CH)          // 512
#define PREP_BLOCKS   120                // 3 kk x 8 c'tiles x 5 djtiles
#define TOTAL_BLOCKS  (GATHER_BLOCKS + PREP_BLOCKS + 1)

// Scratch (__device__ globals per allocation rules)
__device__ float4 g_part4[NB * CH * 3 * ND4];  // partial g sums
__device__ float4 g_W2T4[225 * NC];            // fused weights, transposed
__device__ float  g_bias2[NC];                 // fused bias

// ---------------------------------------------------------------------------
// Mega kernel (R15 verbatim): blocks 0..511 gather; 512..631 prep-GEMM;
// block 632 bias2 + S_k.
// ---------------------------------------------------------------------------
__global__ __launch_bounds__(320, 3) void mega_kernel(
    const int*   __restrict__ x,
    const float* __restrict__ embed_w,
    const float* __restrict__ conv_w,
    const float* __restrict__ conv_b,
    const float* __restrict__ fc3_w,
    const float* __restrict__ fc3_b,
    const float* __restrict__ fc4_w,
    const float* __restrict__ fc4_b,
    const float* __restrict__ fc5_w,
    const float* __restrict__ fc5_b,
    const float* __restrict__ fc_w,
    const float* __restrict__ fc_b)
{
    __shared__ __align__(16) char smu[39744];
    const int bid = blockIdx.x;
    const int tid = threadIdx.x;

    if (bid < GATHER_BLOCKS) {
        // ---------------- Gather (R10 best, verbatim) ----------------
        int*    sidx = (int*)smu;                  // [64]
        float*  sc   = (float*)(smu + 256);        // [3][64]
        float4* sred = (float4*)(smu + 1024);      // [WAYS][3][80]

        const int b     = bid >> 3;
        const int chunk = bid & 7;
        const int d4    = tid % 80;
        const int y     = tid / 80;

        if (tid < 192) {
            const int kk = tid >> 6;
            const int tt = tid & 63;
            const int t  = chunk * TPC + tt;
            const float* wk = (kk == 0) ? fc3_w : (kk == 1) ? fc4_w : fc5_w;
            const int k = kk + 3;
            int lo = t - k + 1; if (lo < 0) lo = 0;
            int hi = t; const int lim = NL - k - 1; if (hi > lim) hi = lim;
            float s = 0.f;
            #pragma unroll 5
            for (int l = lo; l <= hi; l++) s += __ldg(&wk[l]);
            sc[kk * TPC + tt] = s;
        } else if (tid < 256) {
            const int tt = tid - 192;
            sidx[tt] = __ldg(&x[b * NL + chunk * TPC + tt]);
        }
        __syncthreads();

        float4 a0 = make_float4(0.f, 0.f, 0.f, 0.f);
        float4 a1 = a0, a2 = a0;

        if (d4 < ND4) {
            const float4* emb4 = (const float4*)embed_w;
            #pragma unroll
            for (int bb = 0; bb < 2; bb++) {
                int    rix[8];
                float4 v[8];
                #pragma unroll
                for (int j = 0; j < 8; j++) rix[j] = sidx[y * JPER + bb * 8 + j];
                #pragma unroll
                for (int j = 0; j < 8; j++) v[j] = __ldg(&emb4[rix[j] * ND4 + d4]);
                #pragma unroll
                for (int j = 0; j < 8; j++) {
                    const int jj = y * JPER + bb * 8 + j;
                    const float c0 = sc[0 * TPC + jj];
                    const float c1 = sc[1 * TPC + jj];
                    const float c2 = sc[2 * TPC + jj];
                    a0.x = fmaf(c0, v[j].x, a0.x); a0.y = fmaf(c0, v[j].y, a0.y);
                    a0.z = fmaf(c0, v[j].z, a0.z); a0.w = fmaf(c0, v[j].w, a0.w);
                    a1.x = fmaf(c1, v[j].x, a1.x); a1.y = fmaf(c1, v[j].y, a1.y);
                    a1.z = fmaf(c1, v[j].z, a1.z); a1.w = fmaf(c1, v[j].w, a1.w);
                    a2.x = fmaf(c2, v[j].x, a2.x); a2.y = fmaf(c2, v[j].y, a2.y);
                    a2.z = fmaf(c2, v[j].z, a2.z); a2.w = fmaf(c2, v[j].w, a2.w);
                }
            }
        }
        sred[(y * 3 + 0) * 80 + d4] = a0;
        sred[(y * 3 + 1) * 80 + d4] = a1;
        sred[(y * 3 + 2) * 80 + d4] = a2;
        __syncthreads();

        if (tid < 240) {
            const int kk = tid / 80;
            const int dd = tid % 80;
            if (dd < ND4) {
                float4 s = sred[(0 * 3 + kk) * 80 + dd];
                #pragma unroll
                for (int w = 1; w < WAYS; w++) {
                    const float4 v = sred[(w * 3 + kk) * 80 + dd];
                    s.x += v.x; s.y += v.y; s.z += v.z; s.w += v.w;
                }
                g_part4[((b * CH + chunk) * 3 + kk) * ND4 + dd] = s;
            }
        }
    } else if (bid < GATHER_BLOCKS + PREP_BLOCKS) {
        // ---------------- Prep GEMM: W2T[idx][c'] ----------------
        const int pb  = bid - GATHER_BLOCKS;
        const int kk  = pb / 40;
        const int rem = pb % 40;
        const int ct  = rem / 5;
        const int dt  = rem % 5;

        float*  A  = (float*)smu;                  // [16][129] padded
        float4* Bt = (float4*)(smu + 8256);        // [128][15]

        for (int i = tid; i < 16 * 128; i += 320) {
            const int r = i >> 7, cc = i & 127;
            A[r * 129 + cc] = __ldg(&fc_w[(ct * 16 + r) * 384 + kk * 128 + cc]);
        }
        {
            const float4* cw4 = (const float4*)conv_w;
            for (int i = tid; i < 128 * 15; i += 320) {
                const int cc = i / 15, j = i - cc * 15;
                Bt[cc * 15 + j] = __ldg(&cw4[cc * ND4 + dt * 15 + j]);
            }
        }
        __syncthreads();

        if (tid < 240) {
            const int r = tid / 15, j = tid - (tid / 15) * 15;
            float4 acc = make_float4(0.f, 0.f, 0.f, 0.f);
            #pragma unroll 8
            for (int cc = 0; cc < 128; cc++) {
                const float  a = A[r * 129 + cc];
                const float4 v = Bt[cc * 15 + j];
                acc.x = fmaf(a, v.x, acc.x); acc.y = fmaf(a, v.y, acc.y);
                acc.z = fmaf(a, v.z, acc.z); acc.w = fmaf(a, v.w, acc.w);
            }
            g_W2T4[(kk * 75 + dt * 15 + j) * NC + ct * 16 + r] = acc;
        }
    } else {
        // ---------------- bias2 + S_k ----------------
        float* coefvec = (float*)smu;          // [384]
        float* sSk     = (float*)(smu + 1536); // [3]
        const int warp = tid >> 5;
        const int lane = tid & 31;

        if (warp < 3) {
            const float* wks[3] = {fc3_w, fc4_w, fc5_w};
            const float* w = wks[warp];
            const int n = NL - (warp + 3);
            float s = 0.f;
            for (int l = lane; l < n; l += 32) s += __ldg(&w[l]);
            #pragma unroll
            for (int off = 16; off > 0; off >>= 1)
                s += __shfl_xor_sync(0xFFFFFFFFu, s, off);
            if (lane == 0) sSk[warp] = s;
        }
        __syncthreads();

        for (int i = tid; i < 384; i += 320) {
            const int kk = i >> 7, c = i & 127;
            const float bk = (kk == 0) ? fc3_b[0] : (kk == 1) ? fc4_b[0] : fc5_b[0];
            coefvec[i] = __ldg(&conv_b[c]) * sSk[kk] + bk;
        }
        __syncthreads();

        for (int cp = warp; cp < NC; cp += 10) {
            float s = 0.f;
            for (int i = lane; i < 384; i += 32)
                s += __ldg(&fc_w[cp * 384 + i]) * coefvec[i];
            #pragma unroll
            for (int off = 16; off > 0; off >>= 1)
                s += __shfl_xor_sync(0xFFFFFFFFu, s, off);
            if (lane == 0) g_bias2[cp] = s + __ldg(&fc_b[cp]);
        }
    }
}

// ---------------------------------------------------------------------------
// Final kernel, R10-sim grid shape: grid (4 c'-tiles, 64 batches) = 256 blocks,
// 128 threads. Per block: 8-chunk reduce for its batch + fused 225-f4 dot for
// its 32 channels. W2T loads fully coalesced; heavy L2 reuse.
// ---------------------------------------------------------------------------
__global__ __launch_bounds__(128) void final_kernel(float* __restrict__ out)
{
    __shared__ float4 sgs[225];       // reduced g for this batch
    __shared__ float  qp[4 * 32];     // per-warp dot partials

    const int tid  = threadIdx.x;
    const int warp = tid >> 5;
    const int lane = tid & 31;
    const int c0   = blockIdx.x * 32;
    const int b    = blockIdx.y;

    // Reduce CH chunk partials (225 positions, ~2 per thread; 8 indep LDG.128 each)
    #pragma unroll
    for (int i = tid; i < 225; i += 128) {
        const float4* p = &g_part4[b * (CH * 225) + i];
        float4 s = p[0];
        #pragma unroll
        for (int ch = 1; ch < CH; ch++) {
            const float4 v = p[ch * 225];
            s.x += v.x; s.y += v.y; s.z += v.z; s.w += v.w;
        }
        sgs[i] = s;
    }
    __syncthreads();

    // Fused dot: warp q splits 225 as 57|56|56|56, lane = channel
    const int i0 = warp * 56 + (warp > 0);
    const int i1 = (warp == 3) ? 225 : ((warp + 1) * 56 + 1);
    float o = 0.f;
    #pragma unroll 4
    for (int i = i0; i < i1; i++) {
        const float4 w = __ldg(&g_W2T4[i * NC + c0 + lane]);  // coalesced 512B
        const float4 g = sgs[i];                              // broadcast
        o = fmaf(w.x, g.x, o); o = fmaf(w.y, g.y, o);
        o = fmaf(w.z, g.z, o); o = fmaf(w.w, g.w, o);
    }
    qp[warp * 32 + lane] = o;
    __syncthreads();

    if (tid < 32)
        out[b * NC + c0 + tid] = qp[tid] + qp[32 + tid] + qp[64 + tid]
                               + qp[96 + tid] + g_bias2[c0 + tid];
}

// ---------------------------------------------------------------------------
extern "C" void kernel_launch(void* const* d_in, const int* in_sizes, int n_in,
                              void* d_out, int out_size) {
    const int*   x       = (const int*)  d_in[0];
    const float* embed_w = (const float*)d_in[1];
    const float* conv_w  = (const float*)d_in[2];
    const float* conv_b  = (const float*)d_in[3];
    const float* fc3_w   = (const float*)d_in[4];
    const float* fc3_b   = (const float*)d_in[5];
    const float* fc4_w   = (const float*)d_in[6];
    const float* fc4_b   = (const float*)d_in[7];
    const float* fc5_w   = (const float*)d_in[8];
    const float* fc5_b   = (const float*)d_in[9];
    const float* fc_w    = (const float*)d_in[10];
    const float* fc_b    = (const float*)d_in[11];
    float* out = (float*)d_out;

    mega_kernel<<<TOTAL_BLOCKS, 320>>>(x, embed_w, conv_w, conv_b,
                                       fc3_w, fc3_b, fc4_w, fc4_b,
                                       fc5_w, fc5_b, fc_w, fc_b);
    final_kernel<<<dim3(4, NB), 128>>>(out);
}

// round 17
// speedup vs baseline: 1.3902x; 1.3887x over previous
#include <cuda_runtime.h>
#include <cuda_bf16.h>
#include <cstdint>

#define NB 64      // batch
#define NL 512     // sequence length
#define ND 300     // embed dim
#define ND4 75     // float4 lanes per row
#define NC 128     // channels
#define CH 8       // token chunks per batch
#define TPC 64     // tokens per gather block
#define WAYS 4
#define JPER 16    // tokens per way

#define GATHER_BLOCKS (NB * CH)   // 512
#define EPI_BLOCKS    256         // 4 c-tiles x 64 batches

// Scratch (__device__ globals per allocation rules)
__device__ float4 g_part4[NB * CH * 3 * ND4];  // partial g sums
__device__ float  g_h[NB * 384];               // h[b][384]
__device__ int    g_ctr1, g_ctr2, g_ctr3;      // grid-sync counters (reset each run)

// Dynamic smem: one buffer aliased per phase.
//  gather: sidx[0,256) sc[256,1024) sred[1024,16384)
//  sim:    cw_s[0,38400) sg[38400,42000) qp[42000,43536) sSk[43536,43552)
//  fc:     fw_s[0,49664) sh[49664,51200) qp2[51200,51712)
#define FUSED_SMEM 51712

__global__ __launch_bounds__(320, 3) void fused_kernel(
    const int*   __restrict__ x,
    const float* __restrict__ embed_w,
    const float* __restrict__ conv_w,
    const float* __restrict__ conv_b,
    const float* __restrict__ fc3_w,
    const float* __restrict__ fc3_b,
    const float* __restrict__ fc4_w,
    const float* __restrict__ fc4_b,
    const float* __restrict__ fc5_w,
    const float* __restrict__ fc5_b,
    const float* __restrict__ fc_w,
    const float* __restrict__ fc_b,
    float* __restrict__ out)
{
    extern __shared__ __align__(16) char smu[];
    const int bid  = blockIdx.x;
    const int tid  = threadIdx.x;
    const int warp = tid >> 5;
    const int lane = tid & 31;

    // ---------------- Phase 1: gather (R10 best, all 512 blocks) ----------------
    {
        int*    sidx = (int*)smu;
        float*  sc   = (float*)(smu + 256);
        float4* sred = (float4*)(smu + 1024);

        const int b     = bid >> 3;
        const int chunk = bid & 7;
        const int d4    = tid % 80;
        const int y     = tid / 80;

        if (tid < 192) {
            const int kk = tid >> 6;
            const int tt = tid & 63;
            const int t  = chunk * TPC + tt;
            const float* wk = (kk == 0) ? fc3_w : (kk == 1) ? fc4_w : fc5_w;
            const int k = kk + 3;
            int lo = t - k + 1; if (lo < 0) lo = 0;
            int hi = t; const int lim = NL - k - 1; if (hi > lim) hi = lim;
            float s = 0.f;
            #pragma unroll 5
            for (int l = lo; l <= hi; l++) s += __ldg(&wk[l]);
            sc[kk * TPC + tt] = s;
        } else if (tid < 256) {
            const int tt = tid - 192;
            sidx[tt] = __ldg(&x[b * NL + chunk * TPC + tt]);
        }
        __syncthreads();

        float4 a0 = make_float4(0.f, 0.f, 0.f, 0.f);
        float4 a1 = a0, a2 = a0;

        if (d4 < ND4) {
            const float4* emb4 = (const float4*)embed_w;
            #pragma unroll
            for (int bb = 0; bb < 2; bb++) {
                int    rix[8];
                float4 v[8];
                #pragma unroll
                for (int j = 0; j < 8; j++) rix[j] = sidx[y * JPER + bb * 8 + j];
                #pragma unroll
                for (int j = 0; j < 8; j++) v[j] = __ldg(&emb4[rix[j] * ND4 + d4]);
                #pragma unroll
                for (int j = 0; j < 8; j++) {
                    const int jj = y * JPER + bb * 8 + j;
                    const float c0 = sc[0 * TPC + jj];
                    const float c1 = sc[1 * TPC + jj];
                    const float c2 = sc[2 * TPC + jj];
                    a0.x = fmaf(c0, v[j].x, a0.x); a0.y = fmaf(c0, v[j].y, a0.y);
                    a0.z = fmaf(c0, v[j].z, a0.z); a0.w = fmaf(c0, v[j].w, a0.w);
                    a1.x = fmaf(c1, v[j].x, a1.x); a1.y = fmaf(c1, v[j].y, a1.y);
                    a1.z = fmaf(c1, v[j].z, a1.z); a1.w = fmaf(c1, v[j].w, a1.w);
                    a2.x = fmaf(c2, v[j].x, a2.x); a2.y = fmaf(c2, v[j].y, a2.y);
                    a2.z = fmaf(c2, v[j].z, a2.z); a2.w = fmaf(c2, v[j].w, a2.w);
                }
            }
        }
        sred[(y * 3 + 0) * 80 + d4] = a0;
        sred[(y * 3 + 1) * 80 + d4] = a1;
        sred[(y * 3 + 2) * 80 + d4] = a2;
        __syncthreads();

        if (tid < 240) {
            const int kk = tid / 80;
            const int dd = tid % 80;
            if (dd < ND4) {
                float4 s = sred[(0 * 3 + kk) * 80 + dd];
                #pragma unroll
                for (int w = 1; w < WAYS; w++) {
                    const float4 v = sred[(w * 3 + kk) * 80 + dd];
                    s.x += v.x; s.y += v.y; s.z += v.z; s.w += v.w;
                }
                g_part4[((b * CH + chunk) * 3 + kk) * ND4 + dd] = s;
            }
        }
    }
    __syncthreads();
    __threadfence();
    if (tid == 0) atomicAdd(&g_ctr1, 1);

    if (bid >= EPI_BLOCKS) return;   // gather-only blocks exit, freeing SM slots

    // Wait for all 512 gather signals
    if (tid == 0) {
        while (atomicAdd(&g_ctr1, 0) < GATHER_BLOCKS) __nanosleep(64);
    }
    __syncthreads();
    __threadfence();

    // ---------------- Phase 2: sim (R10 best; ct = bid&3, b = bid>>2) ----------------
    const int ct = bid & 3;
    const int b2 = bid >> 2;
    const int c0 = ct * 32;
    {
        float4* cw_s = (float4*)smu;                 // [32][75]
        float4* sg   = (float4*)(smu + 38400);       // [3][75]
        float*  qp   = (float*)(smu + 42000);        // [4][96]
        float*  sSk  = (float*)(smu + 43536);        // [3]

        if (warp < 3) {
            const float* wks[3] = {fc3_w, fc4_w, fc5_w};
            const float* w = wks[warp];
            const int n = NL - (warp + 3);
            float s = 0.f;
            for (int l = lane; l < n; l += 32) s += w[l];
            #pragma unroll
            for (int off = 16; off > 0; off >>= 1)
                s += __shfl_xor_sync(0xFFFFFFFFu, s, off);
            if (lane == 0) sSk[warp] = s;
        }

        {
            const float4* cwg = (const float4*)conv_w;
            #pragma unroll 4
            for (int j = tid; j < 32 * ND4; j += 320)
                cw_s[j] = __ldg(&cwg[c0 * ND4 + j]);
        }
        for (int i = tid; i < 225; i += 320) {
            const float4* p = &g_part4[b2 * (CH * 225) + i];
            float4 s = p[0];
            #pragma unroll
            for (int ch = 1; ch < CH; ch++) {
                const float4 v = p[ch * 225];
                s.x += v.x; s.y += v.y; s.z += v.z; s.w += v.w;
            }
            sg[i] = s;
        }
        __syncthreads();

        if (warp < 4) {   // threads 0-127: (c = lane, q = warp)
            const int c = lane;
            const int q = warp;
            const int i0 = q * 19;
            const int i1 = (q == 3) ? ND4 : (i0 + 19);
            float s0 = 0.f, s1 = 0.f, s2 = 0.f;
            #pragma unroll 4
            for (int i = i0; i < i1; i++) {
                const float4 w  = cw_s[c * ND4 + i];
                const float4 g0 = sg[i];
                const float4 g1 = sg[75 + i];
                const float4 g2 = sg[150 + i];
                s0 = fmaf(w.x, g0.x, s0); s0 = fmaf(w.y, g0.y, s0);
                s0 = fmaf(w.z, g0.z, s0); s0 = fmaf(w.w, g0.w, s0);
                s1 = fmaf(w.x, g1.x, s1); s1 = fmaf(w.y, g1.y, s1);
                s1 = fmaf(w.z, g1.z, s1); s1 = fmaf(w.w, g1.w, s1);
                s2 = fmaf(w.x, g2.x, s2); s2 = fmaf(w.y, g2.y, s2);
                s2 = fmaf(w.z, g2.z, s2); s2 = fmaf(w.w, g2.w, s2);
            }
            qp[q * 96 + 0 * 32 + c] = s0;
            qp[q * 96 + 1 * 32 + c] = s1;
            qp[q * 96 + 2 * 32 + c] = s2;
        }
        __syncthreads();

        if (tid < 96) {
            const int kk = tid / 32;
            const int cc = tid % 32;
            float h = qp[0 * 96 + kk * 32 + cc] + qp[1 * 96 + kk * 32 + cc]
                    + qp[2 * 96 + kk * 32 + cc] + qp[3 * 96 + kk * 32 + cc];
            const float bk = (kk == 0) ? fc3_b[0] : (kk == 1) ? fc4_b[0] : fc5_b[0];
            h += conv_b[c0 + cc] * sSk[kk] + bk;
            g_h[b2 * 384 + kk * NC + c0 + cc] = h;
        }
    }
    __syncthreads();
    __threadfence();
    if (tid == 0) atomicAdd(&g_ctr2, 1);

    // Wait for all 256 sim signals
    if (tid == 0) {
        while (atomicAdd(&g_ctr2, 0) < EPI_BLOCKS) __nanosleep(64);
    }
    __syncthreads();
    __threadfence();

    // ---------------- Phase 3: fc (R10 best) ----------------
    {
        float4* fw_s = (float4*)smu;                 // [32][97] padded
        float4* sh   = (float4*)(smu + 49664);       // [96]
        float*  qp2  = (float*)(smu + 51200);        // [128]

        {
            const float4* fwg = (const float4*)fc_w;
            #pragma unroll 4
            for (int j = tid; j < 32 * 96; j += 320) {
                const int r = j / 96, i = j % 96;
                fw_s[r * 97 + i] = __ldg(&fwg[c0 * 96 + j]);
            }
            if (tid < 96) sh[tid] = ((const float4*)g_h)[b2 * 96 + tid];
        }
        __syncthreads();

        if (warp < 4) {   // threads 0-127: (co = lane, q = warp)
            const int co = lane;
            const int q  = warp;
            float o = 0.f;
            #pragma unroll 4
            for (int i = q * 24; i < q * 24 + 24; i++) {
                const float4 w = fw_s[co * 97 + i];
                const float4 h = sh[i];
                o = fmaf(w.x, h.x, o); o = fmaf(w.y, h.y, o);
                o = fmaf(w.z, h.z, o); o = fmaf(w.w, h.w, o);
            }
            qp2[q * 32 + co] = o;
        }
        __syncthreads();

        if (tid < 32)
            out[b2 * NC + c0 + tid] = qp2[tid] + qp2[32 + tid] + qp2[64 + tid]
                                    + qp2[96 + tid] + fc_b[c0 + tid];
    }

    // ---------------- Counter reset (deterministic across graph replays) ----------------
    __syncthreads();
    __threadfence();
    if (tid == 0) {
        const int v = atomicAdd(&g_ctr3, 1);
        if (v == EPI_BLOCKS - 1) {   // last finisher: everyone else is done reading
            atomicExch(&g_ctr1, 0);
            atomicExch(&g_ctr2, 0);
            atomicExch(&g_ctr3, 0);
        }
    }
}

// ---------------------------------------------------------------------------
extern "C" void kernel_launch(void* const* d_in, const int* in_sizes, int n_in,
                              void* d_out, int out_size) {
    const int*   x       = (const int*)  d_in[0];
    const float* embed_w = (const float*)d_in[1];
    const float* conv_w  = (const float*)d_in[2];
    const float* conv_b  = (const float*)d_in[3];
    const float* fc3_w   = (const float*)d_in[4];
    const float* fc3_b   = (const float*)d_in[5];
    const float* fc4_w   = (const float*)d_in[6];
    const float* fc4_b   = (const float*)d_in[7];
    const float* fc5_w   = (const float*)d_in[8];
    const float* fc5_b   = (const float*)d_in[9];
    const float* fc_w    = (const float*)d_in[10];
    const float* fc_b    = (const float*)d_in[11];
    float* out = (float*)d_out;

    static int smem_set = 0;
    if (!smem_set) {
        cudaFuncSetAttribute(fused_kernel,
                             cudaFuncAttributeMaxDynamicSharedMemorySize, FUSED_SMEM);
        smem_set = 1;
    }

    fused_kernel<<<GATHER_BLOCKS, 320, FUSED_SMEM>>>(
        x, embed_w, conv_w, conv_b, fc3_w, fc3_b, fc4_w, fc4_b,
        fc5_w, fc5_b, fc_w, fc_b, out);
}